// round 17
// baseline (speedup 1.0000x reference)
#include <cuda_runtime.h>
#include <cuda_bf16.h>
#include <math.h>
#include <stdint.h>

#define TT 256
#define BB 64
#define DD 1024
#define HH 2048

#define GRID 128
#define SCTHREADS 256          // scan warps (0-7); total block = 384
#define BLOCKT 384
#define NBD 8                  // n-blocks (each 256 wide)
#define KBD 16                 // k-blocks (each 128 deep)
#define NSL 256
#define KSL 128
#define STEP_ELEMS (BB * HH)   // 131072

typedef unsigned long long ull;

// Scratch (no cudaMalloc allowed)
__device__ __align__(16) float g_xproj[(size_t)TT * BB * HH];     // 128 MB
__device__ __align__(16) float g_part[(size_t)KBD * BB * HH];     // 8 MB
__device__ __align__(16) __nv_bfloat16 g_xhi[(size_t)TT * BB * DD];
__device__ __align__(16) __nv_bfloat16 g_xlo[(size_t)TT * BB * DD];
__device__ __align__(16) __nv_bfloat16 g_whi[(size_t)DD * HH];
__device__ __align__(16) __nv_bfloat16 g_wlo[(size_t)DD * HH];
__device__ __align__(16) __nv_bfloat16 g_hhi[(size_t)BB * HH];    // h(t) hi split
__device__ __align__(16) __nv_bfloat16 g_hlo[(size_t)BB * HH];    // h(t) lo split
__device__ unsigned g_count;          // grid-barrier arrival counter
__device__ unsigned g_xp_done[TT];    // per-t xproj tile completion (16 each)

__device__ __forceinline__ uint32_t smem_to_u32(const void* p) {
    uint32_t a;
    asm("{ .reg .u64 t; cvta.to.shared.u64 t, %1; cvt.u32.u64 %0, t; }"
        : "=r"(a) : "l"(p));
    return a;
}

__device__ __forceinline__ float tanh_fast(float x) {
    float y;
    asm("tanh.approx.f32 %0, %1;" : "=f"(y) : "f"(x));
    return y;
}

// named barriers: 0 = scan warps (256 thr), 1 = xproj warps (128 thr)
#define SBAR() asm volatile("bar.sync 0, 256;" ::: "memory")
#define XBAR() asm volatile("bar.sync 1, 128;" ::: "memory")

// ---- mma.sync / cp.async helpers (sm_80-era PTX, fine at compute_103) --------
__device__ __forceinline__ void ldsm_x4(uint32_t addr, uint32_t* r) {
    asm volatile("ldmatrix.sync.aligned.m8n8.x4.shared.b16 {%0,%1,%2,%3}, [%4];"
                 : "=r"(r[0]), "=r"(r[1]), "=r"(r[2]), "=r"(r[3]) : "r"(addr));
}
__device__ __forceinline__ void ldsm_x4_t(uint32_t addr, uint32_t* r) {
    asm volatile("ldmatrix.sync.aligned.m8n8.x4.trans.shared.b16 {%0,%1,%2,%3}, [%4];"
                 : "=r"(r[0]), "=r"(r[1]), "=r"(r[2]), "=r"(r[3]) : "r"(addr));
}
__device__ __forceinline__ void mma_bf16(float* c, const uint32_t* a,
                                         uint32_t b0, uint32_t b1) {
    asm volatile(
        "mma.sync.aligned.m16n8k16.row.col.f32.bf16.bf16.f32 "
        "{%0,%1,%2,%3}, {%4,%5,%6,%7}, {%8,%9}, {%0,%1,%2,%3};"
        : "+f"(c[0]), "+f"(c[1]), "+f"(c[2]), "+f"(c[3])
        : "r"(a[0]), "r"(a[1]), "r"(a[2]), "r"(a[3]), "r"(b0), "r"(b1));
}
__device__ __forceinline__ void cp_async16(uint32_t saddr, const void* gaddr) {
    asm volatile("cp.async.ca.shared.global [%0], [%1], 16;"
                 :: "r"(saddr), "l"(gaddr) : "memory");
}
#define CP_COMMIT() asm volatile("cp.async.commit_group;" ::: "memory")
#define CP_WAIT(n)  asm volatile("cp.async.wait_group %0;" :: "n"(n) : "memory")

// hi/lo split of 4 floats into packed bf16x2 pairs
__device__ __forceinline__ void split4(const float4& v, uint2& hi, uint2& lo) {
    float s[4] = {v.x, v.y, v.z, v.w};
    __nv_bfloat16 h[4], l[4];
#pragma unroll
    for (int j = 0; j < 4; j++) {
        h[j] = __float2bfloat16(s[j]);
        l[j] = __float2bfloat16(s[j] - __bfloat162float(h[j]));
    }
    __nv_bfloat162 h01 = __halves2bfloat162(h[0], h[1]);
    __nv_bfloat162 h23 = __halves2bfloat162(h[2], h[3]);
    __nv_bfloat162 l01 = __halves2bfloat162(l[0], l[1]);
    __nv_bfloat162 l23 = __halves2bfloat162(l[2], l[3]);
    hi = make_uint2(*(uint32_t*)&h01, *(uint32_t*)&h23);
    lo = make_uint2(*(uint32_t*)&l01, *(uint32_t*)&l23);
}

// ---- sync primitives (proven in R7-R15) ---------------------------------------
__device__ __forceinline__ void spin_ge(unsigned* a, unsigned tgt) {
    unsigned v;
    do {
        asm volatile("ld.acquire.gpu.u32 %0, [%1];" : "=r"(v) : "l"(a));
    } while ((int)(v - tgt) < 0);
}
__device__ __forceinline__ void red_add1(unsigned* a) {
    asm volatile("red.global.gpu.add.u32 [%0], 1;" :: "l"(a) : "memory");
}
// grid barrier among scan warps of all 128 CTAs
__device__ __forceinline__ void grid_barrier(unsigned& target) {
    SBAR();
    if (threadIdx.x == 0) {
        __threadfence();
        red_add1(&g_count);
        target += GRID;
        spin_ge(&g_count, target);
        __threadfence();
    }
    SBAR();
}

__global__ void init_kernel() {
    if (threadIdx.x == 0) g_count = 0u;
    if (threadIdx.x < TT) g_xp_done[threadIdx.x] = 0u;
}

extern __shared__ float smem[];

// smem layout: scan region [0, SC_SMEM); xproj region [SC_SMEM, SC_SMEM+2*XQ_STG)
#define BP 264      // bf16 per W smem row (528 B; conflict-free)
#define AP 136      // bf16 per h smem row
#define SB_HI 0
#define SB_LO (SB_HI + KSL * BP * 2)          // 67584
#define SA_HI (SB_LO + KSL * BP * 2)          // 135168
#define SA_LO (SA_HI + BB * AP * 2)           // 152576
#define SC_SMEM (SA_LO + BB * AP * 2)         // 169984 bytes
// xproj tile stage: A(64x32,pad40) hi/lo = 2*5120; W(32x128,pad136) hi/lo = 2*8704
#define XQ_AHI 0
#define XQ_ALO 5120
#define XQ_WHI 10240
#define XQ_WLO 18944
#define XQ_STG 27648
#define TOT_SMEM (SC_SMEM + 2 * XQ_STG)       // 225280 bytes

__global__ void __launch_bounds__(BLOCKT) scan_kernel(
    const float* __restrict__ state,
    const float* __restrict__ W,
    const float* __restrict__ bias,
    float* __restrict__ out)
{
    char* sm = (char*)smem;
    const int tid = threadIdx.x;
    const int cta = blockIdx.x;
    const int wid = tid >> 5;
    const int lane = tid & 31;
    const int lrow = lane & 15;
    const int lcolq = lane >> 4;

    // =====================================================================
    // xproj warps (8-11): compute g_xproj tiles in t-ascending rounds.
    // tile tau = t*16 + nb; CTA handles tau == cta (mod 128); 32 tiles.
    // Per tile: [64m x 128n], K=1024, 3-term bf16-split, warp-tile 64x32.
    // =====================================================================
    if (wid >= 8) {
        const int wtid = tid - 256;       // 0..127
        const int xw = wid - 8;           // 0..3
        const int wn2 = xw * 32;
        const uint32_t xq = smem_to_u32(sm + SC_SMEM);

        for (int tau = cta; tau < TT * 16; tau += GRID) {
            const int tt = tau >> 4;
            const int nbx = tau & 15;
            const int ncol0 = nbx * 128;

            float cx[4][4][4];
#pragma unroll
            for (int mi = 0; mi < 4; mi++)
#pragma unroll
                for (int j = 0; j < 4; j++)
#pragma unroll
                    for (int q = 0; q < 4; q++) cx[mi][j][q] = 0.0f;

            // loader for k-chunk ch into stage ch&1
            auto xload = [&](int ch) {
                const uint32_t base = xq + (ch & 1) * XQ_STG;
                const int kc = ch * 32;
#pragma unroll
                for (int it = 0; it < 2; it++) {
                    int idx = it * 128 + wtid;        // 0..255 uint4
                    int r = idx >> 2, c8 = (idx & 3) * 8;
                    size_t go = (size_t)(tt * 64 + r) * DD + kc + c8;
                    uint32_t so = (uint32_t)(r * 40 + c8) * 2;
                    cp_async16(base + XQ_AHI + so, &g_xhi[go]);
                    cp_async16(base + XQ_ALO + so, &g_xlo[go]);
                }
#pragma unroll
                for (int it = 0; it < 4; it++) {
                    int idx = it * 128 + wtid;        // 0..511 uint4
                    int kr = idx >> 4, n8 = (idx & 15) * 8;
                    size_t go = (size_t)(kc + kr) * HH + ncol0 + n8;
                    uint32_t so = (uint32_t)(kr * 136 + n8) * 2;
                    cp_async16(base + XQ_WHI + so, &g_whi[go]);
                    cp_async16(base + XQ_WLO + so, &g_wlo[go]);
                }
                CP_COMMIT();
            };

            xload(0);
            xload(1);
            for (int ch = 0; ch < 32; ch++) {
                if (ch == 31) CP_WAIT(0); else CP_WAIT(1);
                XBAR();
                const uint32_t base = xq + (ch & 1) * XQ_STG;
#pragma unroll
                for (int ks = 0; ks < 2; ks++) {
                    uint32_t ah[4][4], al[4][4];
#pragma unroll
                    for (int mi = 0; mi < 4; mi++) {
                        uint32_t off = (uint32_t)((mi * 16 + lrow) * 40 +
                                                  ks * 16 + lcolq * 8) * 2;
                        ldsm_x4(base + XQ_AHI + off, ah[mi]);
                        ldsm_x4(base + XQ_ALO + off, al[mi]);
                    }
                    uint32_t bh[2][4], bl[2][4];
#pragma unroll
                    for (int np = 0; np < 2; np++) {
                        uint32_t off = (uint32_t)((ks * 16 + lrow) * 136 +
                                                  wn2 + np * 16 + lcolq * 8) * 2;
                        ldsm_x4_t(base + XQ_WHI + off, bh[np]);
                        ldsm_x4_t(base + XQ_WLO + off, bl[np]);
                    }
#pragma unroll
                    for (int mi = 0; mi < 4; mi++) {
#pragma unroll
                        for (int j = 0; j < 4; j++) {
                            const int np = j >> 1, pr = (j & 1) * 2;
                            mma_bf16(cx[mi][j], ah[mi], bh[np][pr], bh[np][pr + 1]);
                            mma_bf16(cx[mi][j], ah[mi], bl[np][pr], bl[np][pr + 1]);
                            mma_bf16(cx[mi][j], al[mi], bh[np][pr], bh[np][pr + 1]);
                        }
                    }
                }
                XBAR();
                if (ch + 2 < 32) xload(ch + 2);
            }

            // store tile (+bias) to g_xproj
#pragma unroll
            for (int mi = 0; mi < 4; mi++) {
                const int row0 = tt * 64 + mi * 16 + (lane >> 2);
#pragma unroll
                for (int j = 0; j < 4; j++) {
                    const int col = ncol0 + wn2 + j * 8 + (lane & 3) * 2;
                    const float b0 = __ldg(&bias[col]);
                    const float b1 = __ldg(&bias[col + 1]);
                    *(float2*)&g_xproj[(size_t)row0 * HH + col] =
                        make_float2(cx[mi][j][0] + b0, cx[mi][j][1] + b1);
                    *(float2*)&g_xproj[(size_t)(row0 + 8) * HH + col] =
                        make_float2(cx[mi][j][2] + b0, cx[mi][j][3] + b1);
                }
            }
            XBAR();
            if (wtid == 0) {
                __threadfence();
                red_add1(&g_xp_done[tt]);
            }
        }
        return;   // xproj warps exit; scan warps continue below
    }

    // =====================================================================
    // scan warps (0-7): R11 persistent scan, __syncthreads -> SBAR.
    // =====================================================================
    __nv_bfloat16* sbh = (__nv_bfloat16*)(sm + SB_HI);
    __nv_bfloat16* sbl = (__nv_bfloat16*)(sm + SB_LO);
    __nv_bfloat16* sah = (__nv_bfloat16*)(sm + SA_HI);
    __nv_bfloat16* sal = (__nv_bfloat16*)(sm + SA_LO);

    const int nb = cta & (NBD - 1);
    const int kb = cta >> 3;
    const int nbase = nb * NSL;
    const int k0 = kb * KSL;
    const int wn = wid * 32;

    const uint32_t sbh_b = smem_to_u32(sbh);
    const uint32_t sbl_b = smem_to_u32(sbl);
    const uint32_t sah_b = smem_to_u32(sah);
    const uint32_t sal_b = smem_to_u32(sal);

    // resident W slice [128k x 256n] (once)
#pragma unroll
    for (int i = 0; i < 32; i++) {
        int idx = i * SCTHREADS + tid;
        int k = idx >> 6;
        int n4 = (idx & 63) * 4;
        float4 w = *(const float4*)&W[(size_t)(k0 + k) * HH + nbase + n4];
        uint2 hi, lo;
        split4(w, hi, lo);
        *(uint2*)&sbh[k * BP + n4] = hi;
        *(uint2*)&sbl[k * BP + n4] = lo;
    }
    SBAR();

    unsigned target = 0;

    const int g = cta * SCTHREADS + tid;
    const int em = g >> 9;
    const int ec4 = (g & 511) * 4;
    const size_t eoff = (size_t)em * HH + ec4;

    for (int t = 0; t < TT; t++) {
        // stage h slice [64m x 128k]
        if (t == 0) {
#pragma unroll
            for (int i = 0; i < 8; i++) {
                int idx = i * SCTHREADS + tid;
                int m = idx >> 5;
                int k4 = (idx & 31) * 4;
                float4 h = __ldcg((const float4*)&state[(size_t)m * HH + k0 + k4]);
                uint2 hi, lo;
                split4(h, hi, lo);
                *(uint2*)&sah[m * AP + k4] = hi;
                *(uint2*)&sal[m * AP + k4] = lo;
            }
        } else {
#pragma unroll
            for (int i = 0; i < 4; i++) {
                int idx = i * SCTHREADS + tid;
                int m = idx >> 4;
                int c8 = (idx & 15) * 8;
                size_t goff = (size_t)m * HH + k0 + c8;
                uint32_t soff = (uint32_t)(m * AP + c8) * 2;
                cp_async16(sah_b + soff, &g_hhi[goff]);
                cp_async16(sal_b + soff, &g_hlo[goff]);
            }
            CP_COMMIT();
            CP_WAIT(0);
        }
        SBAR();

        // mma mainloop: 8 k16 steps
        float c[4][4][4];
#pragma unroll
        for (int mi = 0; mi < 4; mi++)
#pragma unroll
            for (int j = 0; j < 4; j++)
#pragma unroll
                for (int q = 0; q < 4; q++) c[mi][j][q] = 0.0f;

#pragma unroll
        for (int ks = 0; ks < 8; ks++) {
            uint32_t ah[4][4], al[4][4];
#pragma unroll
            for (int mi = 0; mi < 4; mi++) {
                uint32_t off = (uint32_t)((mi * 16 + lrow) * AP +
                                          ks * 16 + lcolq * 8) * 2;
                ldsm_x4(sah_b + off, ah[mi]);
                ldsm_x4(sal_b + off, al[mi]);
            }
            uint32_t bh[2][4], bl[2][4];
#pragma unroll
            for (int np = 0; np < 2; np++) {
                uint32_t off = (uint32_t)((ks * 16 + lrow) * BP +
                                          wn + np * 16 + lcolq * 8) * 2;
                ldsm_x4_t(sbh_b + off, bh[np]);
                ldsm_x4_t(sbl_b + off, bl[np]);
            }
#pragma unroll
            for (int mi = 0; mi < 4; mi++) {
#pragma unroll
                for (int j = 0; j < 4; j++) {
                    const int np = j >> 1, pr = (j & 1) * 2;
                    mma_bf16(c[mi][j], ah[mi], bh[np][pr], bh[np][pr + 1]);
                    mma_bf16(c[mi][j], ah[mi], bl[np][pr], bl[np][pr + 1]);
                    mma_bf16(c[mi][j], al[mi], bh[np][pr], bh[np][pr + 1]);
                }
            }
        }

        // write partial [64 x 256] to g_part[kb]
        float* P = g_part + (size_t)kb * STEP_ELEMS;
#pragma unroll
        for (int mi = 0; mi < 4; mi++) {
            const int row0 = mi * 16 + (lane >> 2);
#pragma unroll
            for (int j = 0; j < 4; j++) {
                const int col = nbase + wn + j * 8 + (lane & 3) * 2;
                *(float2*)&P[(size_t)row0 * HH + col] =
                    make_float2(c[mi][j][0], c[mi][j][1]);
                *(float2*)&P[(size_t)(row0 + 8) * HH + col] =
                    make_float2(c[mi][j][2], c[mi][j][3]);
            }
        }

        // gate on xproj[t] being fully produced (16 tiles), then barrier
        if (tid == 0) spin_ge(&g_xp_done[t], 16u);
        grid_barrier(target);

        // epilogue: reduce 16 partials + xproj, tanh, write out + h splits
        {
            const float4 xv = __ldcg((const float4*)&g_xproj[(size_t)t * STEP_ELEMS + eoff]);
            float4 s = __ldcg((const float4*)&g_part[eoff]);
#pragma unroll
            for (int k2 = 1; k2 < KBD; k2++) {
                float4 p = __ldcg((const float4*)&g_part[(size_t)k2 * STEP_ELEMS + eoff]);
                s.x += p.x; s.y += p.y; s.z += p.z; s.w += p.w;
            }
            float4 r;
            r.x = tanh_fast(s.x + xv.x);
            r.y = tanh_fast(s.y + xv.y);
            r.z = tanh_fast(s.z + xv.z);
            r.w = tanh_fast(s.w + xv.w);
            *(float4*)&out[(size_t)t * STEP_ELEMS + eoff] = r;
            uint2 hi, lo;
            split4(r, hi, lo);
            *(uint2*)&g_hhi[eoff] = hi;
            *(uint2*)&g_hlo[eoff] = lo;
            if (t == TT - 1)
                *(float4*)&out[(size_t)TT * STEP_ELEMS + eoff] = r;   // final_state
        }
        grid_barrier(target);
    }
}

// -----------------------------------------------------------------------------
// Elementwise bf16 hi/lo split: hi = bf16(x), lo = bf16(x - hi)
// -----------------------------------------------------------------------------
__global__ void __launch_bounds__(256) convert_split(
    const float* __restrict__ src,
    __nv_bfloat16* __restrict__ hi,
    __nv_bfloat16* __restrict__ lo)
{
    const int i = blockIdx.x * 256 + threadIdx.x;
    float4 v = ((const float4*)src)[i];
    uint2 h, l;
    split4(v, h, l);
    ((uint2*)hi)[i] = h;
    ((uint2*)lo)[i] = l;
}

extern "C" void kernel_launch(void* const* d_in, const int* in_sizes, int n_in,
                              void* d_out, int out_size)
{
    (void)in_sizes; (void)n_in; (void)out_size;
    const float* inputs = (const float*)d_in[0];   // [T,B,D]
    const float* state  = (const float*)d_in[1];   // [B,H]
    const float* W_xh   = (const float*)d_in[2];   // [D,H]
    const float* W_hh   = (const float*)d_in[3];   // [H,H]
    const float* b_h    = (const float*)d_in[4];   // [H]
    float* out = (float*)d_out;   // outputs [T,B,H] then final_state [B,H]

    cudaFuncSetAttribute(scan_kernel, cudaFuncAttributeMaxDynamicSharedMemorySize,
                         TOT_SMEM);

    __nv_bfloat16 *xhi, *xlo, *whi, *wlo;
    cudaGetSymbolAddress((void**)&xhi, g_xhi);
    cudaGetSymbolAddress((void**)&xlo, g_xlo);
    cudaGetSymbolAddress((void**)&whi, g_whi);
    cudaGetSymbolAddress((void**)&wlo, g_wlo);

    // 0) reset sync state (deterministic across graph replays)
    init_kernel<<<1, 256>>>();

    // 1) bf16 hi/lo splits of X and W_xh
    convert_split<<<(TT * BB * DD / 4) / 256, 256>>>(inputs, xhi, xlo);
    convert_split<<<(DD * HH / 4) / 256, 256>>>(W_xh, whi, wlo);

    // 2) fused persistent kernel: scan warps + xproj worker warps
    scan_kernel<<<GRID, BLOCKT, TOT_SMEM>>>(state, W_hh, b_h, out);
}